// round 11
// baseline (speedup 1.0000x reference)
#include <cuda_runtime.h>
#include <cuda_fp16.h>
#include <cstdint>

// ---------------------------------------------------------------------------
// BiLSTM: B=32, T=512, D=512, H=512. out = [B,T,2H] fp32.
// Phase 1: mma.sync tf32 GEMM  xg = W_ih @ x^T (+bias)      [validated R6-R10]
// Phase 2: DIR-PAIRED persistent scan: 64 CTAs x 1024 threads; threads 0-511
//          run fwd, 512-1023 run bwd (independent named-barrier sync), so each
//          SM interleaves two independent serial streams. fp16 single-plane W
//          (R10-validated), fp16 h exchange via L2, nanosleep-backoff barrier.
// ---------------------------------------------------------------------------

#define B_  32
#define T_  512
#define D_  512
#define H_  512
#define G4  2048
#define NBD 64            // CTAs (= arrivals per direction barrier)
#define JT  8             // j columns per CTA per direction
#define SHW 520           // W smem row stride (fp16 elems)
#define HSTR 264          // h region row stride (fp16 elems)

// Scratch (device globals: allocation-free rule)
__device__ float g_xg[2][T_][G4][B_];        // [dir][t][gate*H+j][b]
__device__ __half g_h[2][2][B_][H_];         // [buf][dir][b][j] fp16
__device__ unsigned g_bar2[2];               // per-dir barrier counters

// ---------------------------------------------------------------------------
__device__ __forceinline__ uint32_t f2tf32(float f) {
    uint32_t r;
    asm("cvt.rna.tf32.f32 %0, %1;" : "=r"(r) : "f"(f));
    return r;
}
__device__ __forceinline__ void mma_tf32(float* c, const uint32_t* a, const uint32_t* b) {
    asm volatile(
        "mma.sync.aligned.m16n8k8.row.col.f32.tf32.tf32.f32 "
        "{%0,%1,%2,%3}, {%4,%5,%6,%7}, {%8,%9}, {%0,%1,%2,%3};"
        : "+f"(c[0]), "+f"(c[1]), "+f"(c[2]), "+f"(c[3])
        : "r"(a[0]), "r"(a[1]), "r"(a[2]), "r"(a[3]), "r"(b[0]), "r"(b[1]));
}
__device__ __forceinline__ void mma_f16(float* c, const uint32_t* a, const uint32_t* b) {
    asm volatile(
        "mma.sync.aligned.m16n8k16.row.col.f32.f16.f16.f32 "
        "{%0,%1,%2,%3}, {%4,%5,%6,%7}, {%8,%9}, {%0,%1,%2,%3};"
        : "+f"(c[0]), "+f"(c[1]), "+f"(c[2]), "+f"(c[3])
        : "r"(a[0]), "r"(a[1]), "r"(a[2]), "r"(a[3]), "r"(b[0]), "r"(b[1]));
}
__device__ __forceinline__ void ldmx4(uint32_t* r, uint32_t addr) {
    asm volatile("ldmatrix.sync.aligned.m8n8.x4.shared.b16 {%0,%1,%2,%3}, [%4];"
        : "=r"(r[0]), "=r"(r[1]), "=r"(r[2]), "=r"(r[3]) : "r"(addr));
}
__device__ __forceinline__ void ldmx2(uint32_t* r, uint32_t addr) {
    asm volatile("ldmatrix.sync.aligned.m8n8.x2.shared.b16 {%0,%1}, [%2];"
        : "=r"(r[0]), "=r"(r[1]) : "r"(addr));
}
__device__ __forceinline__ uint32_t smem_u32(const void* p) {
    uint32_t a;
    asm("{ .reg .u64 t; cvta.to.shared.u64 t, %1; cvt.u32.u64 %0, t; }"
        : "=r"(a) : "l"(p));
    return a;
}
__device__ __forceinline__ void cp_async16(uint32_t dst, const void* src) {
    asm volatile("cp.async.cg.shared.global [%0], [%1], 16;" :: "r"(dst), "l"(src));
}
__device__ __forceinline__ uint16_t hfu(__half v) { return __half_as_ushort(v); }
__device__ __forceinline__ void named_bar(int id) {
    asm volatile("bar.sync %0, 512;" :: "r"(id) : "memory");
}

// fast activations (validated R4/R6-R10)
__device__ __forceinline__ float sigf(float x) {
    return __fdividef(1.f, 1.f + __expf(-x));
}
__device__ __forceinline__ float tanhfast(float x) {
    float ax = fabsf(x);
    float e  = __expf(-2.f * ax);
    float t  = __fdividef(1.f - e, 1.f + e);
    return copysignf(t, x);
}

// ---------------------------------------------------------------------------
// Phase 1: tf32 mma.sync GEMM (validated R6-R10). Unchanged.
// ---------------------------------------------------------------------------
#define SSTR 136
#define KCH  32

__global__ __launch_bounds__(256, 2) void proj_mma_kernel(
    const float* __restrict__ x,
    const float* __restrict__ Wf, const float* __restrict__ Wb,
    const float* __restrict__ bihf, const float* __restrict__ bhhf,
    const float* __restrict__ bihb, const float* __restrict__ bhhb)
{
    __shared__ __align__(16) float A_s[KCH * SSTR];
    __shared__ __align__(16) float B_s[KCH * SSTR];

    const int tid  = threadIdx.x;
    const int lane = tid & 31;
    const int wid  = tid >> 5;
    const int mw   = wid & 1;
    const int nw   = wid >> 1;

    if (blockIdx.x == 0 && blockIdx.y == 0) {
        if (tid == 0) { g_bar2[0] = 0u; g_bar2[1] = 0u; }
        uint4* z = (uint4*)&g_h[0][0][0][0];     // 8192 uint4 (both bufs/dirs)
#pragma unroll
        for (int i = 0; i < 32; i++)
            z[tid + (i << 8)] = make_uint4(0, 0, 0, 0);
    }

    const int mtile = blockIdx.y;
    const int dir   = mtile >> 4;
    const int mg0   = (mtile & 15) * 128;
    const int t0    = blockIdx.x * 4;
    const float* W  = dir ? Wb : Wf;

    const int lrow = tid >> 1;
    const int lseg = tid & 1;
    const int bL   = lrow & 31;
    const int dtL  = lrow >> 5;
    const float* Arow = W + (size_t)(mg0 + lrow) * D_;
    const float* Brow = x + ((size_t)bL * T_ + t0 + dtL) * D_;

    float acc[4][4][4];
#pragma unroll
    for (int mi = 0; mi < 4; mi++)
#pragma unroll
        for (int ni = 0; ni < 4; ni++)
#pragma unroll
            for (int q = 0; q < 4; q++) acc[mi][ni][q] = 0.f;

    const int frag_k = lane & 3;
    const int frag_r = lane >> 2;

    for (int c = 0; c < D_ / KCH; c++) {
        const int kc = c * KCH;
#pragma unroll
        for (int it = 0; it < 4; it++) {
            int seg = it * 2 + lseg;
            int k0  = seg * 4;
            float4 av = *(const float4*)(Arow + kc + k0);
            float4 bv = *(const float4*)(Brow + kc + k0);
            A_s[(k0 + 0) * SSTR + lrow] = __uint_as_float(f2tf32(av.x));
            A_s[(k0 + 1) * SSTR + lrow] = __uint_as_float(f2tf32(av.y));
            A_s[(k0 + 2) * SSTR + lrow] = __uint_as_float(f2tf32(av.z));
            A_s[(k0 + 3) * SSTR + lrow] = __uint_as_float(f2tf32(av.w));
            B_s[(k0 + 0) * SSTR + lrow] = __uint_as_float(f2tf32(bv.x));
            B_s[(k0 + 1) * SSTR + lrow] = __uint_as_float(f2tf32(bv.y));
            B_s[(k0 + 2) * SSTR + lrow] = __uint_as_float(f2tf32(bv.z));
            B_s[(k0 + 3) * SSTR + lrow] = __uint_as_float(f2tf32(bv.w));
        }
        __syncthreads();

#pragma unroll
        for (int ks = 0; ks < KCH / 8; ks++) {
            const int kb = ks * 8 + frag_k;
            uint32_t afr[4][4], bfr[4][2];
#pragma unroll
            for (int mi = 0; mi < 4; mi++) {
                int m = mw * 64 + mi * 16 + frag_r;
                afr[mi][0] = __float_as_uint(A_s[kb * SSTR + m]);
                afr[mi][1] = __float_as_uint(A_s[kb * SSTR + m + 8]);
                afr[mi][2] = __float_as_uint(A_s[(kb + 4) * SSTR + m]);
                afr[mi][3] = __float_as_uint(A_s[(kb + 4) * SSTR + m + 8]);
            }
#pragma unroll
            for (int ni = 0; ni < 4; ni++) {
                int n = nw * 32 + ni * 8 + frag_r;
                bfr[ni][0] = __float_as_uint(B_s[kb * SSTR + n]);
                bfr[ni][1] = __float_as_uint(B_s[(kb + 4) * SSTR + n]);
            }
#pragma unroll
            for (int mi = 0; mi < 4; mi++)
#pragma unroll
                for (int ni = 0; ni < 4; ni++)
                    mma_tf32(acc[mi][ni], afr[mi], bfr[ni]);
        }
        __syncthreads();
    }

    const int t  = t0 + nw;
    const int bc = 2 * (lane & 3);
#pragma unroll
    for (int mi = 0; mi < 4; mi++) {
        int g0 = mg0 + mw * 64 + mi * 16 + frag_r;
        float bias0 = dir ? (bihb[g0] + bhhb[g0]) : (bihf[g0] + bhhf[g0]);
        float bias1 = dir ? (bihb[g0 + 8] + bhhb[g0 + 8]) : (bihf[g0 + 8] + bhhf[g0 + 8]);
#pragma unroll
        for (int ni = 0; ni < 4; ni++) {
            int b = ni * 8 + bc;
            *(float2*)&g_xg[dir][t][g0][b] =
                make_float2(acc[mi][ni][0] + bias0, acc[mi][ni][1] + bias0);
            *(float2*)&g_xg[dir][t][g0 + 8][b] =
                make_float2(acc[mi][ni][2] + bias1, acc[mi][ni][3] + bias1);
        }
    }
}

// ---------------------------------------------------------------------------
// Phase 2: dir-paired scan. 64 CTAs x 1024 threads; half h (512 thr) per dir.
// Per half: 16 warps = kw(2) x wm(2) x wn(4); j-tile 8 (m' = gate*8+jj).
// gates[32 m', 32 b] = Whh_blk[32,512] @ h[512,32], fp16 W single plane.
// h regions keyed (kw,wn): warps wm0/wm1 redundantly cp.async identical data
// (benign race, per-warp completion). Spin barrier with nanosleep backoff.
// ---------------------------------------------------------------------------
// per-half smem layout (bytes), half base = hid * HALF_SZ:
#define W0_OFF 0                 // 32 * SHW * 2        = 33280
#define HP_OFF 33280             // 8 regions * 4224    = 33792
#define CS_OFF 67072             // 2*32*36*4           =  9216
#define HN_OFF 76288             // 32*9*4              =  1152
#define HALF_SZ 77440
#define SMEM_TOT (2 * HALF_SZ)   // 154880

__global__ __launch_bounds__(1024, 1) void lstm_scan_kernel(
    const int*   __restrict__ lengths,
    const float* __restrict__ Whf,
    const float* __restrict__ Whb,
    float*       __restrict__ out)
{
    extern __shared__ __align__(16) char sm[];

    const int tid  = threadIdx.x;
    const int hid  = tid >> 9;              // 0 = fwd, 1 = bwd
    const int htid = tid & 511;
    const int lane = tid & 31;
    const int wq   = htid >> 5;             // warp within half (0..15)
    const int dir  = hid;
    const int j0   = blockIdx.x * JT;
    const float* W = dir ? Whb : Whf;
    unsigned* bar  = &g_bar2[dir];
    const int bid1 = 1 + 2 * hid;           // named barrier ids per half
    const int bid2 = 2 + 2 * hid;

    char* hb = sm + hid * HALF_SZ;
    __half* W0_s = (__half*)(hb + W0_OFF);
    float*  C_s  = (float*)(hb + CS_OFF);   // [2][32][36]
    float*  hn_s = (float*)(hb + HN_OFF);   // [32][9]

    // ---- stage W fp16 into smem (once): row m' = gate*8 + jj ----
    for (int i = 0; i < 8; i++) {
        int v = htid + i * 512;             // 0..4095 (32 rows x 128 segs)
        int mrow = v >> 7;
        int seg  = v & 127;
        int gate = mrow >> 3, jj = mrow & 7;
        float4 wv = __ldg((const float4*)(W + (size_t)((gate << 9) + j0 + jj) * D_) + seg);
        uint32_t pA = (uint32_t)hfu(__float2half_rn(wv.x)) |
                      ((uint32_t)hfu(__float2half_rn(wv.y)) << 16);
        uint32_t pB = (uint32_t)hfu(__float2half_rn(wv.z)) |
                      ((uint32_t)hfu(__float2half_rn(wv.w)) << 16);
        *(uint2*)((char*)W0_s + (mrow * SHW + seg * 4) * 2) = make_uint2(pA, pB);
    }
    named_bar(bid1);

    // warp decomposition within half
    const int kw = wq >> 3;                 // K half
    const int wm = (wq >> 2) & 1;           // m16 half
    const int wn = wq & 3;                  // n8 quarter (batch group)
    const int l8 = lane & 7, sel = lane >> 3;
    const uint32_t w0b = smem_u32(W0_s);
    const uint32_t aoff = w0b +
        (uint32_t)((wm * 16 + ((sel & 1) ? 8 : 0) + l8) * SHW
                   + ((sel >> 1) ? 8 : 0) + kw * 256) * 2;
    const uint32_t hreg = smem_u32(hb + HP_OFF) + (uint32_t)(kw * 4 + wn) * 4224;
    const uint32_t boff = hreg + (uint32_t)(l8 * HSTR + ((sel & 1) ? 8 : 0)) * 2;

    // cell identity (first 256 threads of half)
    const int jj = wq & 7;
    const int b  = lane;
    const bool is_cell = (htid < 256);
    const int len = __ldg(&lengths[b]);
    float c_reg = 0.f, h_reg = 0.f;
    int cur = 0;
    unsigned target = 0;

    for (int s = 0; s < T_; s++) {
        const int t = dir ? (T_ - 1 - s) : s;

        // ---- prefetch xg BEFORE barrier (independent of other CTAs) ----
        float xi = 0.f, xf = 0.f, xgv = 0.f, xo = 0.f;
        if (is_cell) {
            const float* xgp = &g_xg[dir][t][0][0];
            xi  = __ldg(xgp + (((0 << 9) + j0 + jj) << 5) + b);
            xf  = __ldg(xgp + (((1 << 9) + j0 + jj) << 5) + b);
            xgv = __ldg(xgp + (((2 << 9) + j0 + jj) << 5) + b);
            xo  = __ldg(xgp + (((3 << 9) + j0 + jj) << 5) + b);
        }

        // ---- per-dir grid barrier (backoff poll) ----
        target += NBD;
        __threadfence();
        named_bar(bid1);
        if (htid == 0) {
            atomicAdd(bar, 1u);
            while (*(volatile unsigned*)bar < target) __nanosleep(64);
            __threadfence();
        }
        named_bar(bid2);

        // ---- stage h region (kw,wn): 8 batches x 256 k fp16 (4 KB) ----
        // wm0/wm1 warps write identical data to the same region (benign).
#pragma unroll
        for (int i = 0; i < 8; i++) {
            const void* src = (const char*)&g_h[cur][dir][wn * 8 + i][kw * 256] + lane * 16;
            cp_async16(hreg + (uint32_t)i * (HSTR * 2) + (uint32_t)lane * 16, src);
        }
        asm volatile("cp.async.commit_group;");
        asm volatile("cp.async.wait_group 0;" ::: "memory");
        __syncwarp();

        // ---- mainloop: 16 k16-steps, single fp16 plane ----
        float c[4] = {0.f, 0.f, 0.f, 0.f};
#pragma unroll
        for (int ks = 0; ks < 16; ks++) {
            uint32_t af[4], bf[2];
            ldmx4(af, aoff + ks * 32);
            ldmx2(bf, boff + ks * 32);
            mma_f16(c, af, bf);
        }

        // ---- partial C -> C_s[kw][m'][b] ----
        {
            int r = lane >> 2, cp2 = (lane & 3) * 2;
            float* Ck = C_s + kw * (32 * 36);
            *(float2*)&Ck[(wm * 16 + r) * 36 + wn * 8 + cp2]     = make_float2(c[0], c[1]);
            *(float2*)&Ck[(wm * 16 + r + 8) * 36 + wn * 8 + cp2] = make_float2(c[2], c[3]);
        }
        named_bar(bid1);

        // ---- LSTM cell for (jj, b): sum K halves ----
        if (is_cell) {
            float ri = C_s[(0 * 8 + jj) * 36 + b] + C_s[(2 * 32 + 0 * 8 + jj) * 36 + b - 32 * 36 + 32 * 36];
            ri = C_s[(0 * 8 + jj) * 36 + b] + C_s[(32 + 0 * 8 + jj) * 36 + b] + xi;
            float rf = C_s[(1 * 8 + jj) * 36 + b] + C_s[(32 + 1 * 8 + jj) * 36 + b] + xf;
            float rg = C_s[(2 * 8 + jj) * 36 + b] + C_s[(32 + 2 * 8 + jj) * 36 + b] + xgv;
            float ro = C_s[(3 * 8 + jj) * 36 + b] + C_s[(32 + 3 * 8 + jj) * 36 + b] + xo;
            float ig = sigf(ri), fg = sigf(rf);
            float gg = tanhfast(rg), og = sigf(ro);
            float cn = fg * c_reg + ig * gg;
            float hn = og * tanhfast(cn);
            if (t < len) { c_reg = cn; h_reg = hn; }
            hn_s[b * 9 + jj] = h_reg;
        }
        named_bar(bid2);

        // ---- out store (first 256 threads of half, 32B runs) ----
        if (is_cell) {
            int bo = htid >> 3, jo = htid & 7;
            out[((size_t)bo * T_ + t) * (2 * H_) + (dir << 9) + j0 + jo] = hn_s[bo * 9 + jo];
        }
        // ---- pack h -> global fp16 (threads 0..31 of half: uint4 per batch) ----
        if (htid < 32) {
            int bb = htid;
            uint32_t p[4];
#pragma unroll
            for (int q = 0; q < 4; q++) {
                __half ha = __float2half_rn(hn_s[bb * 9 + 2 * q]);
                __half hb2 = __float2half_rn(hn_s[bb * 9 + 2 * q + 1]);
                p[q] = (uint32_t)hfu(ha) | ((uint32_t)hfu(hb2) << 16);
            }
            __stcg((uint4*)&g_h[cur ^ 1][dir][bb][j0], make_uint4(p[0], p[1], p[2], p[3]));
        }
        cur ^= 1;
    }
}

// ---------------------------------------------------------------------------
extern "C" void kernel_launch(void* const* d_in, const int* in_sizes, int n_in,
                              void* d_out, int out_size)
{
    const float* x      = (const float*)d_in[0];
    const int*   lens   = (const int*)  d_in[1];
    const float* Wihf   = (const float*)d_in[2];
    const float* Whhf   = (const float*)d_in[3];
    const float* bihf   = (const float*)d_in[4];
    const float* bhhf   = (const float*)d_in[5];
    const float* Wihb   = (const float*)d_in[6];
    const float* Whhb   = (const float*)d_in[7];
    const float* bihb   = (const float*)d_in[8];
    const float* bhhb   = (const float*)d_in[9];
    float* out = (float*)d_out;

    cudaFuncSetAttribute(lstm_scan_kernel,
                         cudaFuncAttributeMaxDynamicSharedMemorySize, SMEM_TOT);

    dim3 pg(T_ / 4, 32);
    proj_mma_kernel<<<pg, 256>>>(x, Wihf, Wihb, bihf, bhhf, bihb, bhhb);

    lstm_scan_kernel<<<NBD, 1024, SMEM_TOT>>>(lens, Whhf, Whhb, out);
}

// round 12
// speedup vs baseline: 1.3944x; 1.3944x over previous
#include <cuda_runtime.h>
#include <cuda_fp16.h>
#include <cstdint>

// ---------------------------------------------------------------------------
// BiLSTM: B=32, T=512, D=512, H=512. out = [B,T,2H] fp32.
// FUSED persistent kernel, 148 CTAs x 512 threads:
//   Phase A: all CTAs project s-blocks q<20 (both dirs) via tf32 mma.
//   Phase B: CTAs 0-63 run the recurrent scan (32/dir, j-tile 16, fp16 mma,
//            R9-style barrier+cp.async exchange); CTAs 64-147 stream the
//            remaining proj tiles in s-order and publish done[q] flags.
// Proj is thereby removed from the critical path (producer outpaces scan).
// ---------------------------------------------------------------------------

#define B_  32
#define T_  512
#define D_  512
#define H_  512
#define G4  2048
#define NSCAN 64          // scan CTAs (32 per dir)
#define NBDS  32          // barrier arrivals per dir
#define JT    16          // j columns per scan CTA
#define SHW  520          // W smem row stride (fp16)
#define HSTR 264          // h region row stride (fp16)
#define QA   20           // phase-A s-block prefix
#define NQ   128

// Scratch (device globals: allocation-free rule)
__device__ float g_xg[2][T_][G4][B_];        // [dir][t][gate*H+j][b]
__device__ __half g_h[2][2][B_][H_];         // [buf][dir][b][j]
__device__ unsigned g_bar2[2];
__device__ unsigned g_ctrA, g_ctrB;
__device__ unsigned g_done[NQ];

// ---------------------------------------------------------------------------
__device__ __forceinline__ uint32_t f2tf32(float f) {
    uint32_t r;
    asm("cvt.rna.tf32.f32 %0, %1;" : "=r"(r) : "f"(f));
    return r;
}
__device__ __forceinline__ void mma_tf32(float* c, const uint32_t* a, const uint32_t* b) {
    asm volatile(
        "mma.sync.aligned.m16n8k8.row.col.f32.tf32.tf32.f32 "
        "{%0,%1,%2,%3}, {%4,%5,%6,%7}, {%8,%9}, {%0,%1,%2,%3};"
        : "+f"(c[0]), "+f"(c[1]), "+f"(c[2]), "+f"(c[3])
        : "r"(a[0]), "r"(a[1]), "r"(a[2]), "r"(a[3]), "r"(b[0]), "r"(b[1]));
}
__device__ __forceinline__ void mma_f16(float* c, const uint32_t* a, const uint32_t* b) {
    asm volatile(
        "mma.sync.aligned.m16n8k16.row.col.f32.f16.f16.f32 "
        "{%0,%1,%2,%3}, {%4,%5,%6,%7}, {%8,%9}, {%0,%1,%2,%3};"
        : "+f"(c[0]), "+f"(c[1]), "+f"(c[2]), "+f"(c[3])
        : "r"(a[0]), "r"(a[1]), "r"(a[2]), "r"(a[3]), "r"(b[0]), "r"(b[1]));
}
__device__ __forceinline__ void ldmx4(uint32_t* r, uint32_t addr) {
    asm volatile("ldmatrix.sync.aligned.m8n8.x4.shared.b16 {%0,%1,%2,%3}, [%4];"
        : "=r"(r[0]), "=r"(r[1]), "=r"(r[2]), "=r"(r[3]) : "r"(addr));
}
__device__ __forceinline__ void ldmx2(uint32_t* r, uint32_t addr) {
    asm volatile("ldmatrix.sync.aligned.m8n8.x2.shared.b16 {%0,%1}, [%2];"
        : "=r"(r[0]), "=r"(r[1]) : "r"(addr));
}
__device__ __forceinline__ uint32_t smem_u32(const void* p) {
    uint32_t a;
    asm("{ .reg .u64 t; cvta.to.shared.u64 t, %1; cvt.u32.u64 %0, t; }"
        : "=r"(a) : "l"(p));
    return a;
}
__device__ __forceinline__ void cp_async16(uint32_t dst, const void* src) {
    asm volatile("cp.async.cg.shared.global [%0], [%1], 16;" :: "r"(dst), "l"(src));
}
__device__ __forceinline__ uint16_t hfu(__half v) { return __half_as_ushort(v); }

// fast activations (validated R4/R6-R11)
__device__ __forceinline__ float sigf(float x) {
    return __fdividef(1.f, 1.f + __expf(-x));
}
__device__ __forceinline__ float tanhfast(float x) {
    float ax = fabsf(x);
    float e  = __expf(-2.f * ax);
    float t  = __fdividef(1.f - e, 1.f + e);
    return copysignf(t, x);
}

// ---------------------------------------------------------------------------
// init: zero h (both bufs), counters, flags
// ---------------------------------------------------------------------------
__global__ void init_kernel() {
    int idx = blockIdx.x * blockDim.x + threadIdx.x;
    if (idx < 2) g_bar2[idx] = 0u;
    if (idx == 2) g_ctrA = 0u;
    if (idx == 3) g_ctrB = 0u;
    if (idx >= 4 && idx < 4 + NQ) g_done[idx - 4] = 0u;
    uint4* z = (uint4*)&g_h[0][0][0][0];     // 8192 uint4
    if (idx < 8192) z[idx] = make_uint4(0, 0, 0, 0);
}

// ---------------------------------------------------------------------------
// smem layout (bytes). Proj region overlaps scan region (phases disjoint).
// ---------------------------------------------------------------------------
#define PA_OFF 0                 // proj A_s: 32*136 floats = 17408
#define PB_OFF 17408             // proj B_s: 17408
#define W0_OFF 0                 // scan W: 64*SHW*2 = 66560
#define HP_OFF 66560             // 8 regions * 4224 = 33792
#define CS_OFF 100352            // 2*64*36*4 = 18432
#define HN_OFF 118784            // 32*17*4 = 2176
#define BC_OFF 120960            // broadcast slot
#define SMEM_TOT 121088

#define SSTR 136
#define KCH  32

// ---------------------------------------------------------------------------
// proj tile (512 threads): 128x128 tf32 tile; 16 warps = 4 mw x 4 nw.
// C[m = dir*2048+g, n' = dt*32+b]; nw == dt. (frag math validated R6-R11)
// ---------------------------------------------------------------------------
__device__ void proj_tile(char* sm, int xtile, int mtile,
    const float* __restrict__ x,
    const float* __restrict__ Wf, const float* __restrict__ Wb,
    const float* __restrict__ bihf, const float* __restrict__ bhhf,
    const float* __restrict__ bihb, const float* __restrict__ bhhb)
{
    float* A_s = (float*)(sm + PA_OFF);
    float* B_s = (float*)(sm + PB_OFF);

    const int tid  = threadIdx.x;
    const int lane = tid & 31;
    const int wid  = tid >> 5;
    const int mw   = wid & 3;          // 0..3
    const int nw   = wid >> 2;         // 0..3 (== dt)

    const int dir  = mtile >> 4;
    const int mg0  = (mtile & 15) * 128;
    const int t0   = xtile * 4;
    const float* W = dir ? Wb : Wf;

    const int lrow = tid >> 2;         // 0..127
    const int ls2  = (tid & 3) * 2;    // seg pair base
    const int bL   = lrow & 31;
    const int dtL  = lrow >> 5;
    const float* Arow = W + (size_t)(mg0 + lrow) * D_;
    const float* Brow = x + ((size_t)bL * T_ + t0 + dtL) * D_;

    float acc[2][4][4];
#pragma unroll
    for (int mi = 0; mi < 2; mi++)
#pragma unroll
        for (int ni = 0; ni < 4; ni++)
#pragma unroll
            for (int q = 0; q < 4; q++) acc[mi][ni][q] = 0.f;

    const int frag_k = lane & 3;
    const int frag_r = lane >> 2;

    for (int c = 0; c < D_ / KCH; c++) {
        const int kc = c * KCH;
#pragma unroll
        for (int it = 0; it < 2; it++) {
            int k0 = (ls2 + it) * 4;
            float4 av = *(const float4*)(Arow + kc + k0);
            float4 bv = *(const float4*)(Brow + kc + k0);
            A_s[(k0 + 0) * SSTR + lrow] = __uint_as_float(f2tf32(av.x));
            A_s[(k0 + 1) * SSTR + lrow] = __uint_as_float(f2tf32(av.y));
            A_s[(k0 + 2) * SSTR + lrow] = __uint_as_float(f2tf32(av.z));
            A_s[(k0 + 3) * SSTR + lrow] = __uint_as_float(f2tf32(av.w));
            B_s[(k0 + 0) * SSTR + lrow] = __uint_as_float(f2tf32(bv.x));
            B_s[(k0 + 1) * SSTR + lrow] = __uint_as_float(f2tf32(bv.y));
            B_s[(k0 + 2) * SSTR + lrow] = __uint_as_float(f2tf32(bv.z));
            B_s[(k0 + 3) * SSTR + lrow] = __uint_as_float(f2tf32(bv.w));
        }
        __syncthreads();

#pragma unroll
        for (int ks = 0; ks < KCH / 8; ks++) {
            const int kb = ks * 8 + frag_k;
            uint32_t afr[2][4], bfr[4][2];
#pragma unroll
            for (int mi = 0; mi < 2; mi++) {
                int m = mw * 32 + mi * 16 + frag_r;
                afr[mi][0] = __float_as_uint(A_s[kb * SSTR + m]);
                afr[mi][1] = __float_as_uint(A_s[kb * SSTR + m + 8]);
                afr[mi][2] = __float_as_uint(A_s[(kb + 4) * SSTR + m]);
                afr[mi][3] = __float_as_uint(A_s[(kb + 4) * SSTR + m + 8]);
            }
#pragma unroll
            for (int ni = 0; ni < 4; ni++) {
                int n = nw * 32 + ni * 8 + frag_r;
                bfr[ni][0] = __float_as_uint(B_s[kb * SSTR + n]);
                bfr[ni][1] = __float_as_uint(B_s[(kb + 4) * SSTR + n]);
            }
#pragma unroll
            for (int mi = 0; mi < 2; mi++)
#pragma unroll
                for (int ni = 0; ni < 4; ni++)
                    mma_tf32(acc[mi][ni], afr[mi], bfr[ni]);
        }
        __syncthreads();
    }

    const int t  = t0 + nw;
    const int bc = 2 * (lane & 3);
#pragma unroll
    for (int mi = 0; mi < 2; mi++) {
        int g0 = mg0 + mw * 32 + mi * 16 + frag_r;
        float bias0 = dir ? (bihb[g0] + bhhb[g0]) : (bihf[g0] + bhhf[g0]);
        float bias1 = dir ? (bihb[g0 + 8] + bhhb[g0 + 8]) : (bihf[g0 + 8] + bhhf[g0 + 8]);
#pragma unroll
        for (int ni = 0; ni < 4; ni++) {
            int b = ni * 8 + bc;
            *(float2*)&g_xg[dir][t][g0][b] =
                make_float2(acc[mi][ni][0] + bias0, acc[mi][ni][1] + bias0);
            *(float2*)&g_xg[dir][t][g0 + 8][b] =
                make_float2(acc[mi][ni][2] + bias1, acc[mi][ni][3] + bias1);
        }
    }
}

// ---------------------------------------------------------------------------
// fused persistent kernel
// ---------------------------------------------------------------------------
__global__ __launch_bounds__(512, 1) void fused_kernel(
    const float* __restrict__ x,
    const int*   __restrict__ lengths,
    const float* __restrict__ Wihf, const float* __restrict__ Whhf,
    const float* __restrict__ bihf, const float* __restrict__ bhhf,
    const float* __restrict__ Wihb, const float* __restrict__ Whhb,
    const float* __restrict__ bihb, const float* __restrict__ bhhb,
    float*       __restrict__ out)
{
    extern __shared__ __align__(16) char sm[];
    int* bc = (int*)(sm + BC_OFF);
    const int tid  = threadIdx.x;
    const int lane = tid & 31;
    const int wq   = tid >> 5;

    // ================= Phase A: all CTAs project s-blocks q < QA ==========
    for (;;) {
        if (tid == 0) *bc = (int)atomicAdd(&g_ctrA, 1u);
        __syncthreads();
        int idx = *bc;
        __syncthreads();
        if (idx >= QA * 32) break;
        int q = idx >> 5, i = idx & 31;
        proj_tile(sm, (i < 16) ? q : (127 - q), i,
                  x, Wihf, Wihb, bihf, bhhf, bihb, bhhb);
        __threadfence();
        __syncthreads();
        if (tid == 0) atomicAdd(&g_done[q], 1u);
    }

    // ================= Phase B workers: remaining proj tiles ==============
    if (blockIdx.x >= NSCAN) {
        for (;;) {
            if (tid == 0) *bc = (int)atomicAdd(&g_ctrB, 1u);
            __syncthreads();
            int idx = *bc;
            __syncthreads();
            if (idx >= (NQ - QA) * 32) return;
            int q = QA + (idx >> 5), i = idx & 31;
            proj_tile(sm, (i < 16) ? q : (127 - q), i,
                      x, Wihf, Wihb, bihf, bhhf, bihb, bhhb);
            __threadfence();
            __syncthreads();
            if (tid == 0) atomicAdd(&g_done[q], 1u);
        }
    }

    // ================= Scan CTAs (0..63): 32 per dir, j-tile 16 ===========
    __half* W0_s = (__half*)(sm + W0_OFF);
    float*  C_s  = (float*)(sm + CS_OFF);   // [2 kw][64 m'][36]
    float*  hn_s = (float*)(sm + HN_OFF);   // [32 b][17]

    const int bx  = blockIdx.x;
    const int dir = bx >> 5;
    const int j0  = (bx & 31) * JT;
    const float* W = dir ? Whhb : Whhf;
    unsigned* bar = &g_bar2[dir];

    __syncthreads();   // phase A used this smem as A_s/B_s

    // ---- stage W fp16 into smem: row m' = gate*16 + jj ----
#pragma unroll
    for (int i = 0; i < 16; i++) {
        int v = tid + i * 512;              // 0..8191 (64 rows x 128 segs)
        int mrow = v >> 7;
        int seg  = v & 127;
        int gate = mrow >> 4, jj = mrow & 15;
        float4 wv = __ldg((const float4*)(W + (size_t)((gate << 9) + j0 + jj) * D_) + seg);
        uint32_t pA = (uint32_t)hfu(__float2half_rn(wv.x)) |
                      ((uint32_t)hfu(__float2half_rn(wv.y)) << 16);
        uint32_t pB = (uint32_t)hfu(__float2half_rn(wv.z)) |
                      ((uint32_t)hfu(__float2half_rn(wv.w)) << 16);
        *(uint2*)((char*)W0_s + (mrow * SHW + seg * 4) * 2) = make_uint2(pA, pB);
    }
    __syncthreads();

    // warp decomposition: kw(2) x wm(2) x wn(4); 2 m16-tiles per warp
    const int kw = wq >> 3;
    const int wm = (wq >> 2) & 1;
    const int wn = wq & 3;
    const int l8 = lane & 7, sel = lane >> 3;
    const uint32_t w0b = smem_u32(W0_s);
    uint32_t aoffs[2];
#pragma unroll
    for (int mt = 0; mt < 2; mt++)
        aoffs[mt] = w0b +
            (uint32_t)((wm * 32 + mt * 16 + ((sel & 1) ? 8 : 0) + l8) * SHW
                       + ((sel >> 1) ? 8 : 0) + kw * 256) * 2;
    const uint32_t hreg = smem_u32(sm + HP_OFF) + (uint32_t)(kw * 4 + wn) * 4224;
    const uint32_t boff = hreg + (uint32_t)(l8 * HSTR + ((sel & 1) ? 8 : 0)) * 2;

    // cell identity: every thread one cell: jj = tid>>5, b = tid&31
    const int jj = wq;                      // 0..15
    const int b  = lane;
    const int len = __ldg(&lengths[b]);
    float c_reg = 0.f, h_reg = 0.f;
    int cur = 0;
    unsigned target = 0;

    for (int s = 0; s < T_; s++) {
        const int t = dir ? (T_ - 1 - s) : s;

        // ---- xg availability gate (once per 4 steps; producer runs ahead) ----
        if ((s & 3) == 0) {
            if (tid == 0) {
                const unsigned q = (unsigned)(s >> 2);
                while (__ldcg((const unsigned*)&g_done[q]) < 32u) { }
            }
            __syncthreads();
        }

        // ---- prefetch xg BEFORE barrier ----
        const float* xgp = &g_xg[dir][t][0][0];
        float xi  = __ldg(xgp + (((0 << 9) + j0 + jj) << 5) + b);
        float xf  = __ldg(xgp + (((1 << 9) + j0 + jj) << 5) + b);
        float xgv = __ldg(xgp + (((2 << 9) + j0 + jj) << 5) + b);
        float xo  = __ldg(xgp + (((3 << 9) + j0 + jj) << 5) + b);

        // ---- per-dir grid barrier (R9-style, no backoff) ----
        target += NBDS;
        __threadfence();
        __syncthreads();
        if (tid == 0) {
            atomicAdd(bar, 1u);
            while (*(volatile unsigned*)bar < target) { }
            __threadfence();
        }
        __syncthreads();

        // ---- stage h region (kw,wn): 8 batches x 256 k fp16 (4 KB) ----
        // wm0/wm1 warps write identical data (benign race; per-warp wait).
#pragma unroll
        for (int i = 0; i < 8; i++) {
            const void* src = (const char*)&g_h[cur][dir][wn * 8 + i][kw * 256] + lane * 16;
            cp_async16(hreg + (uint32_t)i * (HSTR * 2) + (uint32_t)lane * 16, src);
        }
        asm volatile("cp.async.commit_group;");
        asm volatile("cp.async.wait_group 0;" ::: "memory");
        __syncwarp();

        // ---- mainloop: 16 k16-steps, 2 m-tiles ----
        float c0[4] = {0.f, 0.f, 0.f, 0.f};
        float c1[4] = {0.f, 0.f, 0.f, 0.f};
#pragma unroll
        for (int ks = 0; ks < 16; ks++) {
            uint32_t bf[2], a0[4], a1[4];
            ldmx2(bf, boff + ks * 32);
            ldmx4(a0, aoffs[0] + ks * 32);
            ldmx4(a1, aoffs[1] + ks * 32);
            mma_f16(c0, a0, bf);
            mma_f16(c1, a1, bf);
        }

        // ---- partial C -> C_s[kw][m'][b] ----
        {
            int r = lane >> 2, cp2 = (lane & 3) * 2;
            float* Ck = C_s + kw * (64 * 36);
            int r0 = wm * 32 + r;
            *(float2*)&Ck[r0 * 36 + wn * 8 + cp2]        = make_float2(c0[0], c0[1]);
            *(float2*)&Ck[(r0 + 8) * 36 + wn * 8 + cp2]  = make_float2(c0[2], c0[3]);
            *(float2*)&Ck[(r0 + 16) * 36 + wn * 8 + cp2] = make_float2(c1[0], c1[1]);
            *(float2*)&Ck[(r0 + 24) * 36 + wn * 8 + cp2] = make_float2(c1[2], c1[3]);
        }
        __syncthreads();

        // ---- LSTM cell (jj, b): sum K halves ----
        {
            const float* C1p = C_s + 64 * 36;
            float ri = C_s[(0 * 16 + jj) * 36 + b] + C1p[(0 * 16 + jj) * 36 + b] + xi;
            float rf = C_s[(1 * 16 + jj) * 36 + b] + C1p[(1 * 16 + jj) * 36 + b] + xf;
            float rg = C_s[(2 * 16 + jj) * 36 + b] + C1p[(2 * 16 + jj) * 36 + b] + xgv;
            float ro = C_s[(3 * 16 + jj) * 36 + b] + C1p[(3 * 16 + jj) * 36 + b] + xo;
            float ig = sigf(ri), fg = sigf(rf);
            float gg = tanhfast(rg), og = sigf(ro);
            float cn = fg * c_reg + ig * gg;
            float hn = og * tanhfast(cn);
            if (t < len) { c_reg = cn; h_reg = hn; }
            hn_s[b * 17 + jj] = h_reg;
        }
        __syncthreads();

        // ---- out store: thread u: b = u>>4, jo = u&15 (64B runs) ----
        {
            int bo = tid >> 4, jo = tid & 15;
            out[((size_t)bo * T_ + t) * (2 * H_) + (dir << 9) + j0 + jo] =
                hn_s[bo * 17 + jo];
        }
        // ---- pack h -> global fp16 (threads 0..63: uint4 = 8 j) ----
        if (tid < 64) {
            int bb = tid >> 1, h8 = (tid & 1) * 8;
            uint32_t p[4];
#pragma unroll
            for (int q2 = 0; q2 < 4; q2++) {
                __half ha = __float2half_rn(hn_s[bb * 17 + h8 + 2 * q2]);
                __half hb2 = __float2half_rn(hn_s[bb * 17 + h8 + 2 * q2 + 1]);
                p[q2] = (uint32_t)hfu(ha) | ((uint32_t)hfu(hb2) << 16);
            }
            __stcg((uint4*)&g_h[cur ^ 1][dir][bb][j0 + h8],
                   make_uint4(p[0], p[1], p[2], p[3]));
        }
        cur ^= 1;
    }
}

// ---------------------------------------------------------------------------
extern "C" void kernel_launch(void* const* d_in, const int* in_sizes, int n_in,
                              void* d_out, int out_size)
{
    const float* x      = (const float*)d_in[0];
    const int*   lens   = (const int*)  d_in[1];
    const float* Wihf   = (const float*)d_in[2];
    const float* Whhf   = (const float*)d_in[3];
    const float* bihf   = (const float*)d_in[4];
    const float* bhhf   = (const float*)d_in[5];
    const float* Wihb   = (const float*)d_in[6];
    const float* Whhb   = (const float*)d_in[7];
    const float* bihb   = (const float*)d_in[8];
    const float* bhhb   = (const float*)d_in[9];
    float* out = (float*)d_out;

    cudaFuncSetAttribute(fused_kernel,
                         cudaFuncAttributeMaxDynamicSharedMemorySize, SMEM_TOT);

    init_kernel<<<256, 256>>>();

    fused_kernel<<<148, 512, SMEM_TOT>>>(
        x, lens, Wihf, Whhf, bihf, bhhf, Wihb, Whhb, bihb, bhhb, out);
}